// round 10
// baseline (speedup 1.0000x reference)
#include <cuda_runtime.h>
#include <cuda_fp16.h>
#include <cstdint>

#define DDIM     256
#define D4       64
#define KCODES   4096
#define TM       128          // rows per CTA
#define CN       128          // codes per chunk
#define NCHUNK   (KCODES/CN)  // 32
#define KSUB     64           // dims per stage (int8 -> 64 B per code)
#define NSUBC    4            // stages per chunk
#define NITER    (NCHUNK*NSUBC) // 128
#define NSTAGE   8
#define STG_SZ   8192         // B stage bytes (128 codes x 64 int8)
#define THREADS  576          // 2 producer + 16 consumer warps
#define NWARP    18
#define MAXROWS  131072
#define CAP      32
#define SW_SCALE 520192.0f    // 127 * 4096

// ---------------- device global scratch -------------------------------------
__device__ signed char g_zq[(size_t)MAXROWS * DDIM];
__device__ signed char g_wq[KCODES * DDIM];
__device__ float g_wsq[KCODES];
__device__ float g_zsq[MAXROWS];
__device__ float g_c2[MAXROWS];      // -2 / (s_z * s_w)
__device__ float g_marg[MAXROWS];    // rigorous pruning margin
__device__ float g_szrow[MAXROWS];   // per-row quant scale

// ---------------- smem layout (bytes) ---------------------------------------
#define SM_AH    0            // 32768   A int8 [128][256] swizzled
#define SM_B     32768        // 65536   8 stages x 8192
#define SM_WSQ   98304        // 16384
#define SM_ZSQ   114688       // 512
#define SM_MARG  115200       // 512
#define SM_C2    115712       // 512
#define SM_RUNK  116224       // 512
#define SM_CNT   116736       // 512
#define SM_CAND  117248       // 8192    uint16 [128][32]
#define SM_MBAR  125440       // full[8], free[8]
#define SMEM_TOTAL 125568

// ---------------- asm helpers ------------------------------------------------
__device__ __forceinline__ uint32_t smem_u32(const void* p) {
    uint32_t a;
    asm("{ .reg .u64 t; cvta.to.shared.u64 t, %1; cvt.u32.u64 %0, t; }" : "=r"(a) : "l"(p));
    return a;
}
__device__ __forceinline__ void cp_async16(uint32_t sdst, const void* gsrc) {
    asm volatile("cp.async.cg.shared.global [%0], [%1], 16;\n" :: "r"(sdst), "l"(gsrc));
}
__device__ __forceinline__ void cp_commit() { asm volatile("cp.async.commit_group;\n"); }
template <int NN> __device__ __forceinline__ void cp_wait() {
    asm volatile("cp.async.wait_group %0;\n" :: "n"(NN));
}
__device__ __forceinline__ void mbar_init(uint32_t a, uint32_t cnt) {
    asm volatile("mbarrier.init.shared.b64 [%0], %1;" :: "r"(a), "r"(cnt) : "memory");
}
__device__ __forceinline__ void mbar_arrive(uint32_t a) {
    asm volatile("mbarrier.arrive.shared.b64 _, [%0];" :: "r"(a) : "memory");
}
__device__ __forceinline__ void cp_async_mbar_arrive(uint32_t a) {
    asm volatile("cp.async.mbarrier.arrive.noinc.shared.b64 [%0];" :: "r"(a) : "memory");
}
#define MBAR_WAIT(mbar, parity) do {                                            \
    uint32_t _m = (mbar); uint32_t _p = (parity); uint32_t _done;               \
    asm volatile("{\n\t.reg .pred p;\n\t"                                       \
        "mbarrier.try_wait.parity.acquire.cta.shared::cta.b64 p, [%1], %2;\n\t" \
        "selp.b32 %0, 1, 0, p;\n\t}"                                            \
        : "=r"(_done) : "r"(_m), "r"(_p) : "memory");                           \
    if (!_done) {                                                               \
        asm volatile("{\n\t.reg .pred P1;\n\t"                                  \
            "WL_%=:\n\t"                                                        \
            "mbarrier.try_wait.parity.acquire.cta.shared::cta.b64 P1, [%0], %1, 0x989680;\n\t" \
            "@P1 bra.uni WD_%=;\n\t"                                            \
            "bra.uni WL_%=;\n\t"                                                \
            "WD_%=:\n\t}" :: "r"(_m), "r"(_p) : "memory");                      \
    }                                                                           \
} while (0)
#define LDSM4(r, addr)                                                          \
    asm volatile("ldmatrix.sync.aligned.m8n8.x4.shared.b16 {%0,%1,%2,%3}, [%4];"\
        : "=r"((r)[0]), "=r"((r)[1]), "=r"((r)[2]), "=r"((r)[3]) : "r"(addr))
// int8 MMA, s32 accumulate, k=32
#define MMAS8(d, a, b)                                                          \
    asm volatile("mma.sync.aligned.m16n8k32.row.col.s32.s8.s8.s32 "             \
        "{%0,%1,%2,%3}, {%4,%5,%6,%7}, {%8,%9}, {%0,%1,%2,%3};"                 \
        : "+r"((d)[0]), "+r"((d)[1]), "+r"((d)[2]), "+r"((d)[3])                \
        : "r"((a)[0]), "r"((a)[1]), "r"((a)[2]), "r"((a)[3]),                   \
          "r"((b)[0]), "r"((b)[1]))

// order-preserving float<->uint key (for atomicMin over signed floats)
__device__ __forceinline__ uint32_t fkey(float f) {
    uint32_t u = __float_as_uint(f);
    return (u >> 31) ? ~u : (u | 0x80000000u);
}
__device__ __forceinline__ float funkey(uint32_t k) {
    return (k & 0x80000000u) ? __uint_as_float(k & 0x7fffffffu)
                             : __uint_as_float(~k);
}

// ---------------- preprocessing ----------------------------------------------
// per-row stats: z_sq (summation order is part of the proven tie structure —
// DO NOT change), max|z|, sum|z| -> scale, margin, dequant constant
__global__ void zstat_kernel(const float* __restrict__ z, int N) {
    int n = blockIdx.x * blockDim.x + threadIdx.x;
    if (n < N) {
        const float4* row = reinterpret_cast<const float4*>(z) + (size_t)n * D4;
        float s = 0.f, ma = 0.f, sa = 0.f;
#pragma unroll 8
        for (int i = 0; i < D4; i++) {
            float4 v = row[i];
            s += v.x * v.x; s += v.y * v.y; s += v.z * v.z; s += v.w * v.w;
            ma = fmaxf(ma, fabsf(v.x)); ma = fmaxf(ma, fabsf(v.y));
            ma = fmaxf(ma, fabsf(v.z)); ma = fmaxf(ma, fabsf(v.w));
            sa += fabsf(v.x) + fabsf(v.y) + fabsf(v.z) + fabsf(v.w);
        }
        g_zsq[n] = s;
        float sz = 127.0f / fmaxf(ma, 1e-30f);
        g_szrow[n] = sz;
        g_c2[n] = -2.0f / (sz * SW_SCALE);
        // rigorous margin (x1.25 safety, fp32-eval slack 4e-5):
        //   2*( eps_w * sum|z| + 0.0625 * 0.5/s_z ) * 1.25 + slack
        g_marg[n] = 2.403e-6f * sa + 0.078125f / sz + 4e-5f;
    }
}
__global__ void zquant_kernel(const float4* __restrict__ z4, int n4) {
    int i = blockIdx.x * blockDim.x + threadIdx.x;
    if (i < n4) {
        float s = g_szrow[i >> 6];
        float4 v = z4[i];
        int a = __float2int_rn(v.x * s), b = __float2int_rn(v.y * s);
        int c = __float2int_rn(v.z * s), d = __float2int_rn(v.w * s);
        a = max(-127, min(127, a)); b = max(-127, min(127, b));
        c = max(-127, min(127, c)); d = max(-127, min(127, d));
        char4 q = { (signed char)a, (signed char)b, (signed char)c, (signed char)d };
        reinterpret_cast<char4*>(g_zq)[i] = q;
    }
}
__global__ void wquant_kernel(const float4* __restrict__ w4, int n4) {
    int i = blockIdx.x * blockDim.x + threadIdx.x;
    if (i < n4) {
        float4 v = w4[i];
        int a = __float2int_rn(v.x * SW_SCALE), b = __float2int_rn(v.y * SW_SCALE);
        int c = __float2int_rn(v.z * SW_SCALE), d = __float2int_rn(v.w * SW_SCALE);
        a = max(-127, min(127, a)); b = max(-127, min(127, b));
        c = max(-127, min(127, c)); d = max(-127, min(127, d));
        char4 q = { (signed char)a, (signed char)b, (signed char)c, (signed char)d };
        reinterpret_cast<char4*>(g_wq)[i] = q;
    }
}
__global__ void wsq_kernel(const float* __restrict__ w) {
    int k = blockIdx.x * blockDim.x + threadIdx.x;
    if (k < KCODES) {
        const float4* row = reinterpret_cast<const float4*>(w) + (size_t)k * D4;
        float s = 0.f;
#pragma unroll 8
        for (int i = 0; i < D4; i++) {
            float4 v = row[i];
            s += v.x * v.x; s += v.y * v.y; s += v.z * v.z; s += v.w * v.w;
        }
        g_wsq[k] = s;
    }
}

// ---------------- main fused kernel -------------------------------------------
__global__ __launch_bounds__(THREADS, 1)
void vq_main(const float* __restrict__ z, const float* __restrict__ w,
             float* __restrict__ out, int N, int write_idx) {
    extern __shared__ char sm[];
    const uint32_t smu = smem_u32(sm);
    const int tid  = threadIdx.x;
    const int wid  = tid >> 5;
    const int l    = tid & 31;
    const int rowBase = blockIdx.x * TM;

    float*     wsq_s  = reinterpret_cast<float*>(sm + SM_WSQ);
    float*     zsq_s  = reinterpret_cast<float*>(sm + SM_ZSQ);
    float*     marg_s = reinterpret_cast<float*>(sm + SM_MARG);
    float*     c2_s   = reinterpret_cast<float*>(sm + SM_C2);
    uint32_t*  runk_s = reinterpret_cast<uint32_t*>(sm + SM_RUNK);
    int*       cnt_s  = reinterpret_cast<int*>(sm + SM_CNT);
    uint16_t*  cand_s = reinterpret_cast<uint16_t*>(sm + SM_CAND);

    if (tid == 0) {
#pragma unroll
        for (int s = 0; s < NSTAGE; s++) {
            mbar_init(smu + SM_MBAR + s * 8, 64);        // full: 64 producer threads
            mbar_init(smu + SM_MBAR + 64 + s * 8, 16);   // free: 16 consumer warps
        }
    }

    // ---- prologue: A int8 (32KB) + wsq via cp.async; per-row tables --------
#pragma unroll
    for (int i = 0; i < 4; i++) {
        int idx = tid + i * THREADS;
        if (idx < 2048) {
            int r = idx >> 4, g = idx & 15;
            uint32_t sw = r * 256 + ((g ^ (r & 7)) << 4);
            cp_async16(smu + SM_AH + sw,
                       g_zq + (((size_t)(rowBase + r)) << 8) + (g << 4));
        }
    }
#pragma unroll
    for (int i = 0; i < 2; i++) {
        int idx = tid + i * THREADS;
        if (idx < 1024) cp_async16(smu + SM_WSQ + idx * 16, g_wsq + idx * 4);
    }
    cp_commit();
    if (tid < TM) {
        zsq_s[tid]  = g_zsq[rowBase + tid];
        marg_s[tid] = g_marg[rowBase + tid];
        c2_s[tid]   = g_c2[rowBase + tid];
        runk_s[tid] = 0xFFFFFFFFu;
        cnt_s[tid]  = 0;
    }
    cp_wait<0>();
    __syncthreads();     // A, wsq, tables visible; mbarriers initialized

    if (wid < 2) {
        // ==================== producers: 64 threads =========================
        const int t = tid;
        int ph = 1;
        for (int it = 0; it < NITER; ++it) {
            const int s = it & (NSTAGE - 1);
            MBAR_WAIT(smu + SM_MBAR + 64 + s * 8, ph);
            if (s == NSTAGE - 1) ph ^= 1;
            const int cb = (it >> 2) * CN;
            const int d0 = (it & 3) * KSUB;
            const uint32_t sB = smu + SM_B + s * STG_SZ;
#pragma unroll
            for (int i = 0; i < 8; i++) {
                int idx = t + i * 64;
                int n = idx >> 2, g = idx & 3;    // code n (0..127), 16B group g
                uint32_t sw = n * 64 + ((g ^ (n & 3)) << 4);
                cp_async16(sB + sw, g_wq + (((size_t)(cb + n)) << 8) + d0 + (g << 4));
            }
            cp_async_mbar_arrive(smu + SM_MBAR + s * 8);
        }
    } else {
        // ==================== consumers: 16 warps ===========================
        const int cw = wid - 2;
        const int wr = cw >> 2;       // 0..3  (32 rows each)
        const int wc = cw & 3;        // 0..3  (32 codes each)
        const int lx = l & 7, lhi = l >> 4, l3 = l & 3, l15 = l & 15;
        const int l8 = (l >> 3) & 1;

        uint32_t aBase[2];
#pragma unroll
        for (int mt = 0; mt < 2; mt++)
            aBase[mt] = smu + SM_AH + (wr * 32 + mt * 16 + l15) * 256;
        uint32_t bBase[2];
#pragma unroll
        for (int p = 0; p < 2; p++)
            bBase[p] = (uint32_t)((wc * 32 + p * 16 + (l & 7) + (lhi << 3)) * 64);

        // per-thread row constants (2 mt x 2 rh rows)
        float c2r[2][2], mrg[2][2];
        int   rowi[2][2];
#pragma unroll
        for (int mt = 0; mt < 2; mt++)
#pragma unroll
            for (int rh = 0; rh < 2; rh++) {
                const int row = wr * 32 + mt * 16 + (l >> 2) + rh * 8;
                rowi[mt][rh] = row;
                c2r[mt][rh]  = c2_s[row];
                mrg[mt][rh]  = marg_s[row];
            }

        int acc[2][4][4];
        int phF = 0, itg = 0;

        for (int c = 0; c < NCHUNK; ++c) {
#pragma unroll
            for (int mt = 0; mt < 2; mt++)
#pragma unroll
                for (int nt = 0; nt < 4; nt++)
#pragma unroll
                    for (int j = 0; j < 4; j++) acc[mt][nt][j] = 0;

            for (int sub = 0; sub < NSUBC; ++sub, ++itg) {
                const int s = itg & (NSTAGE - 1);
                MBAR_WAIT(smu + SM_MBAR + s * 8, phF);
                if (s == NSTAGE - 1) phF ^= 1;
                const uint32_t stg = smu + SM_B + s * STG_SZ;
#pragma unroll
                for (int h = 0; h < 2; ++h) {     // 2 x 32-dim (byte) slices
                    uint32_t ah[2][4], bh[4][2];
                    const uint32_t offA =
                        (uint32_t)(((sub * 4 + h * 2 + lhi) ^ lx) << 4);
#pragma unroll
                    for (int mt = 0; mt < 2; mt++) LDSM4(ah[mt], aBase[mt] + offA);
                    const uint32_t offB =
                        (uint32_t)(((h * 2 + l8) ^ l3) << 4);
#pragma unroll
                    for (int p = 0; p < 2; p++) {
                        uint32_t t4[4];
                        LDSM4(t4, stg + bBase[p] + offB);
                        bh[2 * p][0] = t4[0]; bh[2 * p][1] = t4[1];
                        bh[2 * p + 1][0] = t4[2]; bh[2 * p + 1][1] = t4[3];
                    }
#pragma unroll
                    for (int mt = 0; mt < 2; mt++)
#pragma unroll
                        for (int nt = 0; nt < 4; nt++)
                            MMAS8(acc[mt][nt], ah[mt], bh[nt]);
                }
                if (l == 0) mbar_arrive(smu + SM_MBAR + 64 + s * 8);
            }

            // ---- epilogue: E'(k) = wsq + c2*dot_int ; margin collect -------
            const int cb = c * CN + wc * 32 + l3 * 2;
            // convert s32 acc -> float E in place (store float bits)
#pragma unroll
            for (int mt = 0; mt < 2; mt++)
#pragma unroll
                for (int nt = 0; nt < 4; nt++)
#pragma unroll
                    for (int rh = 0; rh < 2; rh++)
#pragma unroll
                        for (int cc = 0; cc < 2; cc++)
                            acc[mt][nt][rh * 2 + cc] = __float_as_int(
                                fmaf(__int2float_rn(acc[mt][nt][rh * 2 + cc]),
                                     c2r[mt][rh], wsq_s[cb + nt * 8 + cc]));
            // phase 1: per-row local min -> shared running min (key space)
#pragma unroll
            for (int mt = 0; mt < 2; mt++)
#pragma unroll
                for (int rh = 0; rh < 2; rh++) {
                    float lm = __int_as_float(acc[mt][0][rh * 2]);
#pragma unroll
                    for (int nt = 0; nt < 4; nt++)
#pragma unroll
                        for (int cc = 0; cc < 2; cc++) {
                            const float e = __int_as_float(acc[mt][nt][rh * 2 + cc]);
                            lm = (e < lm) ? e : lm;
                        }
                    const uint32_t key = fkey(lm);
                    if (key < runk_s[rowi[mt][rh]]) atomicMin(&runk_s[rowi[mt][rh]], key);
                }
            // phase 2: append candidates within margin of (current) min
#pragma unroll
            for (int mt = 0; mt < 2; mt++)
#pragma unroll
                for (int rh = 0; rh < 2; rh++) {
                    const int row = rowi[mt][rh];
                    const float thr = funkey(runk_s[row]) + mrg[mt][rh];
#pragma unroll
                    for (int nt = 0; nt < 4; nt++)
#pragma unroll
                        for (int cc = 0; cc < 2; cc++) {
                            const float e = __int_as_float(acc[mt][nt][rh * 2 + cc]);
                            if (e <= thr) {
                                int pos = atomicAdd(&cnt_s[row], 1);
                                if (pos < CAP)
                                    cand_s[row * CAP + pos] =
                                        (uint16_t)(cb + nt * 8 + cc);
                            }
                        }
                }
        }
    }

    __syncthreads();   // pass-1 complete; candidate lists visible to all warps

    // ==================== pass 2: exact fp32 rescore (all 18 warps) =========
    const float4* w4 = reinterpret_cast<const float4*>(w);
    for (int r = wid; r < TM; r += NWARP) {
        const float zs = zsq_s[r];
        const float4* zr = reinterpret_cast<const float4*>(z) + (size_t)(rowBase + r) * D4;
        const float4 za = zr[l * 2], zb = zr[l * 2 + 1];
        const int cnt = cnt_s[r];
        const bool fullscan = (cnt > CAP);
        const int total = fullscan ? KCODES : cnt;
        float bd = 3.4e38f;
        int   bi = 0x7fffffff;
        for (int i = 0; i < total; i++) {
            const int code = fullscan ? i : (int)cand_s[r * CAP + i];
            const float4* wr4 = w4 + (size_t)code * D4;
            const float4 wa = wr4[l * 2], wb = wr4[l * 2 + 1];
            float p = za.x * wa.x;
            p += za.y * wa.y; p += za.z * wa.z; p += za.w * wa.w;
            p += zb.x * wb.x; p += zb.y * wb.y; p += zb.z * wb.z; p += zb.w * wb.w;
#pragma unroll
            for (int off = 16; off > 0; off >>= 1)
                p += __shfl_xor_sync(0xffffffff, p, off);
            const float dist = (zs - 2.0f * p) + wsq_s[code];
            if (dist < bd || (dist == bd && code < bi)) { bd = dist; bi = code; }
        }
        if (write_idx && l == 0)
            out[(size_t)N * DDIM + rowBase + r] = (float)bi;
        const float4* src = w4 + (size_t)bi * D4;
        float4* dst = reinterpret_cast<float4*>(out) + (size_t)(rowBase + r) * D4;
        dst[l]      = src[l];
        dst[l + 32] = src[l + 32];
    }
}

// -------------------------------------------------------------------------------
extern "C" void kernel_launch(void* const* d_in, const int* in_sizes, int n_in,
                              void* d_out, int out_size) {
    const float* z = (const float*)d_in[0];
    const float* w = (const float*)d_in[1];
    float* out = (float*)d_out;
    const int N = in_sizes[0] / DDIM;

    cudaFuncSetAttribute(vq_main, cudaFuncAttributeMaxDynamicSharedMemorySize, SMEM_TOTAL);
    const int write_idx = (out_size >= N * DDIM + N) ? 1 : 0;

    wquant_kernel<<<(KCODES * D4 + 255) / 256, 256>>>((const float4*)w, KCODES * D4);
    wsq_kernel<<<(KCODES + 255) / 256, 256>>>(w);
    zstat_kernel<<<(N + 255) / 256, 256>>>(z, N);
    zquant_kernel<<<((size_t)N * D4 + 255) / 256, 256>>>((const float4*)z, N * D4);
    vq_main<<<N / TM, THREADS, SMEM_TOTAL>>>(z, w, out, N, write_idx);
}

// round 12
// speedup vs baseline: 10.4708x; 10.4708x over previous
#include <cuda_runtime.h>
#include <cuda_fp16.h>
#include <cstdint>

#define DDIM     256
#define D4       64
#define KCODES   4096
#define TM       128          // rows per CTA
#define CN       128          // codes per chunk
#define NCHUNK   (KCODES/CN)  // 32
#define KSUB     64           // dims per stage
#define NSUBC    4            // stages per chunk
#define NITER    (NCHUNK*NSUBC) // 128
#define NSTAGE   4
#define STG_SZ   16384        // B stage bytes (128 codes x 64 dims f16)
#define THREADS  576          // 2 producer + 16 consumer warps
#define NWARP    18
#define MAXROWS  131072
#define CAP      32

// ---------------- device global scratch -------------------------------------
__device__ __half g_zh[(size_t)MAXROWS * DDIM];
__device__ __half g_wh[KCODES * DDIM];
__device__ float  g_wsq[KCODES];
__device__ float  g_zsq[MAXROWS];

// ---------------- smem layout (bytes) ---------------------------------------
#define SM_AH    0            // 65536   A_hi [128][256] f16 swizzled
#define SM_B     65536        // 65536   4 stages x 16384
#define SM_WSQ   131072       // 16384
#define SM_ZSQ   147456       // 512
#define SM_MARG  147968       // 512
#define SM_RUNK  148480       // 512
#define SM_CNT   148992       // 512
#define SM_CAND  149504       // 8192    uint16 [128][32]
#define SM_MBAR  157696       // full[4], free[4]
#define SMEM_TOTAL 157824

// ---------------- asm helpers ------------------------------------------------
__device__ __forceinline__ uint32_t smem_u32(const void* p) {
    uint32_t a;
    asm("{ .reg .u64 t; cvta.to.shared.u64 t, %1; cvt.u32.u64 %0, t; }" : "=r"(a) : "l"(p));
    return a;
}
__device__ __forceinline__ void cp_async16(uint32_t sdst, const void* gsrc) {
    asm volatile("cp.async.cg.shared.global [%0], [%1], 16;\n" :: "r"(sdst), "l"(gsrc));
}
__device__ __forceinline__ void cp_commit() { asm volatile("cp.async.commit_group;\n"); }
template <int NN> __device__ __forceinline__ void cp_wait() {
    asm volatile("cp.async.wait_group %0;\n" :: "n"(NN));
}
__device__ __forceinline__ void mbar_init(uint32_t a, uint32_t cnt) {
    asm volatile("mbarrier.init.shared.b64 [%0], %1;" :: "r"(a), "r"(cnt) : "memory");
}
__device__ __forceinline__ void mbar_arrive(uint32_t a) {
    asm volatile("mbarrier.arrive.shared.b64 _, [%0];" :: "r"(a) : "memory");
}
__device__ __forceinline__ void cp_async_mbar_arrive(uint32_t a) {
    asm volatile("cp.async.mbarrier.arrive.noinc.shared.b64 [%0];" :: "r"(a) : "memory");
}
#define MBAR_WAIT(mbar, parity) do {                                            \
    uint32_t _m = (mbar); uint32_t _p = (parity); uint32_t _done;               \
    asm volatile("{\n\t.reg .pred p;\n\t"                                       \
        "mbarrier.try_wait.parity.acquire.cta.shared::cta.b64 p, [%1], %2;\n\t" \
        "selp.b32 %0, 1, 0, p;\n\t}"                                            \
        : "=r"(_done) : "r"(_m), "r"(_p) : "memory");                           \
    if (!_done) {                                                               \
        asm volatile("{\n\t.reg .pred P1;\n\t"                                  \
            "WL_%=:\n\t"                                                        \
            "mbarrier.try_wait.parity.acquire.cta.shared::cta.b64 P1, [%0], %1, 0x989680;\n\t" \
            "@P1 bra.uni WD_%=;\n\t"                                            \
            "bra.uni WL_%=;\n\t"                                                \
            "WD_%=:\n\t}" :: "r"(_m), "r"(_p) : "memory");                      \
    }                                                                           \
} while (0)
#define LDSM4(r, addr)                                                          \
    asm volatile("ldmatrix.sync.aligned.m8n8.x4.shared.b16 {%0,%1,%2,%3}, [%4];"\
        : "=r"((r)[0]), "=r"((r)[1]), "=r"((r)[2]), "=r"((r)[3]) : "r"(addr))
#define MMA16816(d, a, b)                                                       \
    asm volatile("mma.sync.aligned.m16n8k16.row.col.f32.f16.f16.f32 "           \
        "{%0,%1,%2,%3}, {%4,%5,%6,%7}, {%8,%9}, {%0,%1,%2,%3};"                 \
        : "+f"((d)[0]), "+f"((d)[1]), "+f"((d)[2]), "+f"((d)[3])                \
        : "r"((a)[0]), "r"((a)[1]), "r"((a)[2]), "r"((a)[3]),                   \
          "r"((b)[0]), "r"((b)[1]))

// order-preserving float<->uint key (for atomicMin over signed floats)
__device__ __forceinline__ uint32_t fkey(float f) {
    uint32_t u = __float_as_uint(f);
    return (u >> 31) ? ~u : (u | 0x80000000u);
}
__device__ __forceinline__ float funkey(uint32_t k) {
    return (k & 0x80000000u) ? __uint_as_float(k & 0x7fffffffu)
                             : __uint_as_float(~k);
}

// ---------------- preprocessing ----------------------------------------------
// fused: z -> fp16 hi limb AND z_sq (summation order is part of the proven
// tie structure — do not change)
__global__ void zprep_kernel(const float* __restrict__ z, int N) {
    int n = blockIdx.x * blockDim.x + threadIdx.x;
    if (n < N) {
        const float4* row = reinterpret_cast<const float4*>(z) + (size_t)n * D4;
        uint2* dst = reinterpret_cast<uint2*>(g_zh) + (size_t)n * D4;
        float s = 0.f;
#pragma unroll 8
        for (int i = 0; i < D4; i++) {
            float4 v = row[i];
            s += v.x * v.x; s += v.y * v.y; s += v.z * v.z; s += v.w * v.w;
            __half2 h01 = __halves2half2(__float2half_rn(v.x), __float2half_rn(v.y));
            __half2 h23 = __halves2half2(__float2half_rn(v.z), __float2half_rn(v.w));
            uint2 uh = { *reinterpret_cast<uint32_t*>(&h01),
                         *reinterpret_cast<uint32_t*>(&h23) };
            dst[i] = uh;
        }
        g_zsq[n] = s;
    }
}
__global__ void decomp_w_kernel(const float4* __restrict__ w4, int n4) {
    int i = blockIdx.x * blockDim.x + threadIdx.x;
    if (i < n4) {
        float4 v = w4[i];
        v.x *= 4096.f; v.y *= 4096.f; v.z *= 4096.f; v.w *= 4096.f;  // exact 2^12
        __half2 h01 = __halves2half2(__float2half_rn(v.x), __float2half_rn(v.y));
        __half2 h23 = __halves2half2(__float2half_rn(v.z), __float2half_rn(v.w));
        uint2 uh = { *reinterpret_cast<uint32_t*>(&h01), *reinterpret_cast<uint32_t*>(&h23) };
        reinterpret_cast<uint2*>(g_wh)[i] = uh;
    }
}
__global__ void wsq_kernel(const float* __restrict__ w) {
    int k = blockIdx.x * blockDim.x + threadIdx.x;
    if (k < KCODES) {
        const float4* row = reinterpret_cast<const float4*>(w) + (size_t)k * D4;
        float s = 0.f;
#pragma unroll 8
        for (int i = 0; i < D4; i++) {
            float4 v = row[i];
            s += v.x * v.x; s += v.y * v.y; s += v.z * v.z; s += v.w * v.w;
        }
        g_wsq[k] = s;
    }
}

// ---------------- main fused kernel -------------------------------------------
__global__ __launch_bounds__(THREADS, 1)
void vq_main(const float* __restrict__ z, const float* __restrict__ w,
             float* __restrict__ out, int N, int write_idx) {
    extern __shared__ char sm[];
    const uint32_t smu = smem_u32(sm);
    const int tid  = threadIdx.x;
    const int wid  = tid >> 5;
    const int l    = tid & 31;
    const int rowBase = blockIdx.x * TM;

    float*     wsq_s  = reinterpret_cast<float*>(sm + SM_WSQ);
    float*     zsq_s  = reinterpret_cast<float*>(sm + SM_ZSQ);
    float*     marg_s = reinterpret_cast<float*>(sm + SM_MARG);
    uint32_t*  runk_s = reinterpret_cast<uint32_t*>(sm + SM_RUNK);
    int*       cnt_s  = reinterpret_cast<int*>(sm + SM_CNT);
    uint16_t*  cand_s = reinterpret_cast<uint16_t*>(sm + SM_CAND);

    if (tid == 0) {
#pragma unroll
        for (int s = 0; s < NSTAGE; s++) {
            mbar_init(smu + SM_MBAR + s * 8, 64);        // full: 64 producer threads
            mbar_init(smu + SM_MBAR + 32 + s * 8, 16);   // free: 16 consumer warps
        }
    }

    // ---- prologue: A_hi + wsq via cp.async; zsq / margin / counters --------
#pragma unroll
    for (int i = 0; i < 8; i++) {
        int idx = tid + i * THREADS;
        if (idx < 4096) {
            int r = idx >> 5, g = idx & 31;
            uint32_t sw = r * 512 + ((g ^ (r & 7)) << 4);
            cp_async16(smu + SM_AH + sw, g_zh + (((size_t)(rowBase + r)) << 8) + (g << 3));
        }
    }
#pragma unroll
    for (int i = 0; i < 2; i++) {
        int idx = tid + i * THREADS;
        if (idx < 1024) cp_async16(smu + SM_WSQ + idx * 16, g_wsq + idx * 4);
    }
    cp_commit();
    if (tid < TM) {
        float zsv = g_zsq[rowBase + tid];
        zsq_s[tid]  = zsv;
        // rigorous pruning margin: 2*(2^-10 * sqrt(zs) * ||w||max) + slack
        marg_s[tid] = 1.526e-5f * sqrtf(zsv) + 3e-5f;
        runk_s[tid] = 0xFFFFFFFFu;
        cnt_s[tid]  = 0;
    }
    cp_wait<0>();
    __syncthreads();     // A, wsq, zsq, counters visible; mbarriers initialized

    if (wid < 2) {
        // ==================== producers: 64 threads =========================
        const int t = tid;
        int ph = 1;
        for (int it = 0; it < NITER; ++it) {
            const int s = it & (NSTAGE - 1);
            MBAR_WAIT(smu + SM_MBAR + 32 + s * 8, ph);
            if (s == NSTAGE - 1) ph ^= 1;
            const int cb = (it >> 2) * CN;
            const int d0 = (it & 3) * KSUB;
            const uint32_t sB = smu + SM_B + s * STG_SZ;
#pragma unroll
            for (int i = 0; i < 16; i++) {
                int idx = t + i * 64;
                int n = idx >> 3, g = idx & 7;
                uint32_t sw = n * 128 + ((g ^ (n & 7)) << 4);
                cp_async16(sB + sw, g_wh + (((size_t)(cb + n)) << 8) + d0 + (g << 3));
            }
            cp_async_mbar_arrive(smu + SM_MBAR + s * 8);
        }
    } else {
        // ==================== consumers: 16 warps ===========================
        const int cw = wid - 2;
        const int wr = cw >> 2;       // 0..3  (32 rows each)
        const int wc = cw & 3;        // 0..3  (32 codes each)
        const int lx = l & 7, lhi = l >> 4, l3 = l & 3, l15 = l & 15;

        uint32_t aBaseH[2];
#pragma unroll
        for (int mt = 0; mt < 2; mt++)
            aBaseH[mt] = smu + SM_AH + (wr * 32 + mt * 16 + l15) * 512;
        uint32_t bBase[2];
#pragma unroll
        for (int p = 0; p < 2; p++)
            bBase[p] = (uint32_t)((wc * 32 + p * 16 + l15) * 128);

        float accBuf[2][2][4][4];
        int phF = 0, itg = 0;

        // deferred epilogue phase 1: convert acc -> E in place; update row min
        auto epiPhase1 = [&](float (*ac)[4][4], int cPrev) {
            const int cb = cPrev * CN + wc * 32 + l3 * 2;
#pragma unroll
            for (int mt = 0; mt < 2; mt++)
#pragma unroll
                for (int nt = 0; nt < 4; nt++)
#pragma unroll
                    for (int rh = 0; rh < 2; rh++)
#pragma unroll
                        for (int cc = 0; cc < 2; cc++)
                            ac[mt][nt][rh * 2 + cc] =
                                fmaf(ac[mt][nt][rh * 2 + cc], -0x1p-11f,
                                     wsq_s[cb + nt * 8 + cc]);
#pragma unroll
            for (int mt = 0; mt < 2; mt++)
#pragma unroll
                for (int rh = 0; rh < 2; rh++) {
                    const int row = wr * 32 + mt * 16 + (l >> 2) + rh * 8;
                    float lm = ac[mt][0][rh * 2];
#pragma unroll
                    for (int nt = 0; nt < 4; nt++)
#pragma unroll
                        for (int cc = 0; cc < 2; cc++) {
                            const float e = ac[mt][nt][rh * 2 + cc];
                            lm = (e < lm) ? e : lm;
                        }
                    const uint32_t key = fkey(lm);
                    if (key < runk_s[row]) atomicMin(&runk_s[row], key);
                }
        };
        // deferred epilogue phase 2: collect candidates within margin
        auto epiPhase2 = [&](float (*ac)[4][4], int cPrev) {
            const int cb = cPrev * CN + wc * 32 + l3 * 2;
#pragma unroll
            for (int mt = 0; mt < 2; mt++)
#pragma unroll
                for (int rh = 0; rh < 2; rh++) {
                    const int row = wr * 32 + mt * 16 + (l >> 2) + rh * 8;
                    const float thr = funkey(runk_s[row]) + marg_s[row];
#pragma unroll
                    for (int nt = 0; nt < 4; nt++)
#pragma unroll
                        for (int cc = 0; cc < 2; cc++) {
                            const float e = ac[mt][nt][rh * 2 + cc];
                            if (e <= thr) {
                                int pos = atomicAdd(&cnt_s[row], 1);
                                if (pos < CAP)
                                    cand_s[row * CAP + pos] =
                                        (uint16_t)(cb + nt * 8 + cc);
                            }
                        }
                }
        };

        for (int c = 0; c < NCHUNK; ++c) {
            const int buf = c & 1;
            float (*acc)[4][4] = accBuf[buf];
#pragma unroll
            for (int mt = 0; mt < 2; mt++)
#pragma unroll
                for (int nt = 0; nt < 4; nt++)
#pragma unroll
                    for (int j = 0; j < 4; j++) acc[mt][nt][j] = 0.f;

            for (int sub = 0; sub < NSUBC; ++sub, ++itg) {
                const int s = itg & (NSTAGE - 1);
                MBAR_WAIT(smu + SM_MBAR + s * 8, phF);
                if (s == NSTAGE - 1) phF ^= 1;
                const uint32_t stg = smu + SM_B + s * STG_SZ;
#pragma unroll
                for (int h = 0; h < 4; ++h) {     // 4 x 16-dim slices per stage
                    uint32_t ah[2][4], bh[4][2];
                    const uint32_t cxa =
                        (uint32_t)(((sub * 8 + h * 2 + lhi) ^ lx) << 4);
#pragma unroll
                    for (int mt = 0; mt < 2; mt++) LDSM4(ah[mt], aBaseH[mt] + cxa);
                    const uint32_t ob = (uint32_t)(((h * 2 + lhi) ^ lx) << 4);
#pragma unroll
                    for (int p = 0; p < 2; p++) {
                        uint32_t tmp[4];
                        LDSM4(tmp, stg + bBase[p] + ob);
                        bh[2 * p][0] = tmp[0]; bh[2 * p][1] = tmp[2];
                        bh[2 * p + 1][0] = tmp[1]; bh[2 * p + 1][1] = tmp[3];
                    }
#pragma unroll
                    for (int mt = 0; mt < 2; mt++)
#pragma unroll
                        for (int nt = 0; nt < 4; nt++)
                            MMA16816(acc[mt][nt], ah[mt], bh[nt]);
                }
                if (l == 0) mbar_arrive(smu + SM_MBAR + 32 + s * 8);
                // deferred epilogue of previous chunk overlaps this chunk's MMAs
                if (c > 0 && sub == 0) epiPhase1(accBuf[buf ^ 1], c - 1);
                if (c > 0 && sub == 1) epiPhase2(accBuf[buf ^ 1], c - 1);
            }
        }
        // final chunk's epilogue
        epiPhase1(accBuf[(NCHUNK - 1) & 1], NCHUNK - 1);
        epiPhase2(accBuf[(NCHUNK - 1) & 1], NCHUNK - 1);
    }

    __syncthreads();   // pass-1 complete; candidate lists visible to all warps

    // ==================== pass 2: exact fp32 rescore (all 18 warps) =========
    const float4* w4 = reinterpret_cast<const float4*>(w);
    for (int r = wid; r < TM; r += NWARP) {
        const float zs = zsq_s[r];
        const float4* zr = reinterpret_cast<const float4*>(z) + (size_t)(rowBase + r) * D4;
        const float4 za = zr[l * 2], zb = zr[l * 2 + 1];
        const int cnt = cnt_s[r];
        const bool fullscan = (cnt > CAP);
        const int total = fullscan ? KCODES : cnt;
        float bd = 3.4e38f;
        int   bi = 0x7fffffff;
        for (int i = 0; i < total; i++) {
            const int code = fullscan ? i : (int)cand_s[r * CAP + i];
            const float4* wr4 = w4 + (size_t)code * D4;
            const float4 wa = wr4[l * 2], wb = wr4[l * 2 + 1];
            float p = za.x * wa.x;
            p += za.y * wa.y; p += za.z * wa.z; p += za.w * wa.w;
            p += zb.x * wb.x; p += zb.y * wb.y; p += zb.z * wb.z; p += zb.w * wb.w;
#pragma unroll
            for (int off = 16; off > 0; off >>= 1)
                p += __shfl_xor_sync(0xffffffff, p, off);
            const float dist = (zs - 2.0f * p) + wsq_s[code];
            if (dist < bd || (dist == bd && code < bi)) { bd = dist; bi = code; }
        }
        if (write_idx && l == 0)
            out[(size_t)N * DDIM + rowBase + r] = (float)bi;
        const float4* src = w4 + (size_t)bi * D4;
        float4* dst = reinterpret_cast<float4*>(out) + (size_t)(rowBase + r) * D4;
        dst[l]      = src[l];
        dst[l + 32] = src[l + 32];
    }
}

// -------------------------------------------------------------------------------
extern "C" void kernel_launch(void* const* d_in, const int* in_sizes, int n_in,
                              void* d_out, int out_size) {
    const float* z = (const float*)d_in[0];
    const float* w = (const float*)d_in[1];
    float* out = (float*)d_out;
    const int N = in_sizes[0] / DDIM;

    cudaFuncSetAttribute(vq_main, cudaFuncAttributeMaxDynamicSharedMemorySize, SMEM_TOTAL);
    const int write_idx = (out_size >= N * DDIM + N) ? 1 : 0;

    decomp_w_kernel<<<(KCODES * D4 + 255) / 256, 256>>>((const float4*)w, KCODES * D4);
    wsq_kernel<<<(KCODES + 255) / 256, 256>>>(w);
    zprep_kernel<<<(N + 255) / 256, 256>>>(z, N);
    vq_main<<<N / TM, THREADS, SMEM_TOTAL>>>(z, w, out, N, write_idx);
}

// round 13
// speedup vs baseline: 16.9801x; 1.6217x over previous
#include <cuda_runtime.h>
#include <cuda_fp16.h>
#include <cstdint>

#define DDIM     256
#define D4       64
#define KCODES   4096
#define TM       128          // rows per CTA
#define CN       128          // codes per chunk
#define NCHUNK   (KCODES/CN)  // 32
#define KSUB     64           // dims per stage
#define NSUBC    4            // stages per chunk
#define NITER    (NCHUNK*NSUBC) // 128
#define NSTAGE   4
#define STG_SZ   16384        // B stage bytes (128 codes x 64 dims f16)
#define THREADS  576          // 2 producer + 16 consumer warps
#define NWARP    18
#define MAXROWS  131072
#define CAP      32

// ---------------- device global scratch -------------------------------------
__device__ __half g_zh[(size_t)MAXROWS * DDIM];
__device__ __half g_wh[KCODES * DDIM];
__device__ float  g_wsq[KCODES];
__device__ float  g_zsq[MAXROWS];

// ---------------- smem layout (bytes) ---------------------------------------
#define SM_AH    0            // 65536   A_hi [128][256] f16 swizzled
#define SM_B     65536        // 65536   4 stages x 16384
#define SM_WSQ   131072       // 16384
#define SM_ZSQ   147456       // 512
#define SM_MARG  147968       // 512
#define SM_RUNK  148480       // 512
#define SM_CNT   148992       // 512
#define SM_CAND  149504       // 8192    uint16 [128][32]
#define SM_MBAR  157696       // full[4], free[4]
#define SMEM_TOTAL 157824

// ---------------- asm helpers ------------------------------------------------
__device__ __forceinline__ uint32_t smem_u32(const void* p) {
    uint32_t a;
    asm("{ .reg .u64 t; cvta.to.shared.u64 t, %1; cvt.u32.u64 %0, t; }" : "=r"(a) : "l"(p));
    return a;
}
__device__ __forceinline__ void cp_async16(uint32_t sdst, const void* gsrc) {
    asm volatile("cp.async.cg.shared.global [%0], [%1], 16;\n" :: "r"(sdst), "l"(gsrc));
}
__device__ __forceinline__ void cp_commit() { asm volatile("cp.async.commit_group;\n"); }
template <int NN> __device__ __forceinline__ void cp_wait() {
    asm volatile("cp.async.wait_group %0;\n" :: "n"(NN));
}
__device__ __forceinline__ void mbar_init(uint32_t a, uint32_t cnt) {
    asm volatile("mbarrier.init.shared.b64 [%0], %1;" :: "r"(a), "r"(cnt) : "memory");
}
__device__ __forceinline__ void mbar_arrive(uint32_t a) {
    asm volatile("mbarrier.arrive.shared.b64 _, [%0];" :: "r"(a) : "memory");
}
__device__ __forceinline__ void cp_async_mbar_arrive(uint32_t a) {
    asm volatile("cp.async.mbarrier.arrive.noinc.shared.b64 [%0];" :: "r"(a) : "memory");
}
#define MBAR_WAIT(mbar, parity) do {                                            \
    uint32_t _m = (mbar); uint32_t _p = (parity); uint32_t _done;               \
    asm volatile("{\n\t.reg .pred p;\n\t"                                       \
        "mbarrier.try_wait.parity.acquire.cta.shared::cta.b64 p, [%1], %2;\n\t" \
        "selp.b32 %0, 1, 0, p;\n\t}"                                            \
        : "=r"(_done) : "r"(_m), "r"(_p) : "memory");                           \
    if (!_done) {                                                               \
        asm volatile("{\n\t.reg .pred P1;\n\t"                                  \
            "WL_%=:\n\t"                                                        \
            "mbarrier.try_wait.parity.acquire.cta.shared::cta.b64 P1, [%0], %1, 0x989680;\n\t" \
            "@P1 bra.uni WD_%=;\n\t"                                            \
            "bra.uni WL_%=;\n\t"                                                \
            "WD_%=:\n\t}" :: "r"(_m), "r"(_p) : "memory");                      \
    }                                                                           \
} while (0)
#define LDSM4(r, addr)                                                          \
    asm volatile("ldmatrix.sync.aligned.m8n8.x4.shared.b16 {%0,%1,%2,%3}, [%4];"\
        : "=r"((r)[0]), "=r"((r)[1]), "=r"((r)[2]), "=r"((r)[3]) : "r"(addr))
#define MMA16816(d, a, b)                                                       \
    asm volatile("mma.sync.aligned.m16n8k16.row.col.f32.f16.f16.f32 "           \
        "{%0,%1,%2,%3}, {%4,%5,%6,%7}, {%8,%9}, {%0,%1,%2,%3};"                 \
        : "+f"((d)[0]), "+f"((d)[1]), "+f"((d)[2]), "+f"((d)[3])                \
        : "r"((a)[0]), "r"((a)[1]), "r"((a)[2]), "r"((a)[3]),                   \
          "r"((b)[0]), "r"((b)[1]))

// order-preserving float<->uint key (for atomicMin over signed floats)
__device__ __forceinline__ uint32_t fkey(float f) {
    uint32_t u = __float_as_uint(f);
    return (u >> 31) ? ~u : (u | 0x80000000u);
}
__device__ __forceinline__ float funkey(uint32_t k) {
    return (k & 0x80000000u) ? __uint_as_float(k & 0x7fffffffu)
                             : __uint_as_float(~k);
}

// ---------------- preprocessing ----------------------------------------------
// fused: z -> fp16 hi limb AND z_sq (summation order is part of the proven
// tie structure — do not change)
__global__ void zprep_kernel(const float* __restrict__ z, int N) {
    int n = blockIdx.x * blockDim.x + threadIdx.x;
    if (n < N) {
        const float4* row = reinterpret_cast<const float4*>(z) + (size_t)n * D4;
        uint2* dst = reinterpret_cast<uint2*>(g_zh) + (size_t)n * D4;
        float s = 0.f;
#pragma unroll 8
        for (int i = 0; i < D4; i++) {
            float4 v = row[i];
            s += v.x * v.x; s += v.y * v.y; s += v.z * v.z; s += v.w * v.w;
            __half2 h01 = __halves2half2(__float2half_rn(v.x), __float2half_rn(v.y));
            __half2 h23 = __halves2half2(__float2half_rn(v.z), __float2half_rn(v.w));
            uint2 uh = { *reinterpret_cast<uint32_t*>(&h01),
                         *reinterpret_cast<uint32_t*>(&h23) };
            dst[i] = uh;
        }
        g_zsq[n] = s;
    }
}
__global__ void decomp_w_kernel(const float4* __restrict__ w4, int n4) {
    int i = blockIdx.x * blockDim.x + threadIdx.x;
    if (i < n4) {
        float4 v = w4[i];
        v.x *= 4096.f; v.y *= 4096.f; v.z *= 4096.f; v.w *= 4096.f;  // exact 2^12
        __half2 h01 = __halves2half2(__float2half_rn(v.x), __float2half_rn(v.y));
        __half2 h23 = __halves2half2(__float2half_rn(v.z), __float2half_rn(v.w));
        uint2 uh = { *reinterpret_cast<uint32_t*>(&h01), *reinterpret_cast<uint32_t*>(&h23) };
        reinterpret_cast<uint2*>(g_wh)[i] = uh;
    }
}
__global__ void wsq_kernel(const float* __restrict__ w) {
    int k = blockIdx.x * blockDim.x + threadIdx.x;
    if (k < KCODES) {
        const float4* row = reinterpret_cast<const float4*>(w) + (size_t)k * D4;
        float s = 0.f;
#pragma unroll 8
        for (int i = 0; i < D4; i++) {
            float4 v = row[i];
            s += v.x * v.x; s += v.y * v.y; s += v.z * v.z; s += v.w * v.w;
        }
        g_wsq[k] = s;
    }
}

// ---------------- consumer helpers (all statically inlined) -------------------
struct ConsCtx {
    uint32_t aBaseH0, aBaseH1, bBase0, bBase1;
    uint32_t smu;
    int wr, wc, lx, lhi, l3, l;
};

__device__ __forceinline__ void do_stage(float (&acc)[2][4][4], const ConsCtx& cx,
                                         uint32_t stg, int sub) {
#pragma unroll
    for (int h = 0; h < 4; ++h) {
        uint32_t ah0[4], ah1[4], bh[4][2];
        const uint32_t cxa = (uint32_t)(((sub * 8 + h * 2 + cx.lhi) ^ cx.lx) << 4);
        LDSM4(ah0, cx.aBaseH0 + cxa);
        LDSM4(ah1, cx.aBaseH1 + cxa);
        const uint32_t ob = (uint32_t)(((h * 2 + cx.lhi) ^ cx.lx) << 4);
        {
            uint32_t tmp[4];
            LDSM4(tmp, stg + cx.bBase0 + ob);
            bh[0][0] = tmp[0]; bh[0][1] = tmp[2];
            bh[1][0] = tmp[1]; bh[1][1] = tmp[3];
            LDSM4(tmp, stg + cx.bBase1 + ob);
            bh[2][0] = tmp[0]; bh[2][1] = tmp[2];
            bh[3][0] = tmp[1]; bh[3][1] = tmp[3];
        }
#pragma unroll
        for (int nt = 0; nt < 4; nt++) {
            MMA16816(acc[0][nt], ah0, bh[nt]);
            MMA16816(acc[1][nt], ah1, bh[nt]);
        }
    }
}

// phase 1: convert acc -> E in place; record group-local mins; update row min
__device__ __forceinline__ void epi1(float (&ac)[2][4][4], float (&lm)[2][2],
                                     const ConsCtx& cx, int cPrev,
                                     const float* wsq_s, uint32_t* runk_s) {
    const int cb = cPrev * CN + cx.wc * 32 + cx.l3 * 2;
#pragma unroll
    for (int mt = 0; mt < 2; mt++)
#pragma unroll
        for (int nt = 0; nt < 4; nt++)
#pragma unroll
            for (int rh = 0; rh < 2; rh++)
#pragma unroll
                for (int cc = 0; cc < 2; cc++)
                    ac[mt][nt][rh * 2 + cc] =
                        fmaf(ac[mt][nt][rh * 2 + cc], -0x1p-11f,
                             wsq_s[cb + nt * 8 + cc]);
#pragma unroll
    for (int mt = 0; mt < 2; mt++)
#pragma unroll
        for (int rh = 0; rh < 2; rh++) {
            const int row = cx.wr * 32 + mt * 16 + (cx.l >> 2) + rh * 8;
            float m = ac[mt][0][rh * 2];
#pragma unroll
            for (int nt = 0; nt < 4; nt++)
#pragma unroll
                for (int cc = 0; cc < 2; cc++) {
                    const float e = ac[mt][nt][rh * 2 + cc];
                    m = (e < m) ? e : m;
                }
            lm[mt][rh] = m;
            const uint32_t key = fkey(m);
            if (key < runk_s[row]) atomicMin(&runk_s[row], key);
        }
}

// phase 2: collect candidates within margin (guarded by group-local min)
__device__ __forceinline__ void epi2(float (&ac)[2][4][4], float (&lm)[2][2],
                                     const ConsCtx& cx, int cPrev,
                                     const float* marg_s, uint32_t* runk_s,
                                     int* cnt_s, uint16_t* cand_s) {
    const int cb = cPrev * CN + cx.wc * 32 + cx.l3 * 2;
#pragma unroll
    for (int mt = 0; mt < 2; mt++)
#pragma unroll
        for (int rh = 0; rh < 2; rh++) {
            const int row = cx.wr * 32 + mt * 16 + (cx.l >> 2) + rh * 8;
            const float thr = funkey(runk_s[row]) + marg_s[row];
            if (lm[mt][rh] <= thr) {
#pragma unroll
                for (int nt = 0; nt < 4; nt++)
#pragma unroll
                    for (int cc = 0; cc < 2; cc++) {
                        const float e = ac[mt][nt][rh * 2 + cc];
                        if (e <= thr) {
                            int pos = atomicAdd(&cnt_s[row], 1);
                            if (pos < CAP)
                                cand_s[row * CAP + pos] =
                                    (uint16_t)(cb + nt * 8 + cc);
                        }
                    }
            }
        }
}

// ---------------- main fused kernel -------------------------------------------
__global__ __launch_bounds__(THREADS, 1)
void vq_main(const float* __restrict__ z, const float* __restrict__ w,
             float* __restrict__ out, int N, int write_idx) {
    extern __shared__ char sm[];
    const uint32_t smu = smem_u32(sm);
    const int tid  = threadIdx.x;
    const int wid  = tid >> 5;
    const int l    = tid & 31;
    const int rowBase = blockIdx.x * TM;

    float*     wsq_s  = reinterpret_cast<float*>(sm + SM_WSQ);
    float*     zsq_s  = reinterpret_cast<float*>(sm + SM_ZSQ);
    float*     marg_s = reinterpret_cast<float*>(sm + SM_MARG);
    uint32_t*  runk_s = reinterpret_cast<uint32_t*>(sm + SM_RUNK);
    int*       cnt_s  = reinterpret_cast<int*>(sm + SM_CNT);
    uint16_t*  cand_s = reinterpret_cast<uint16_t*>(sm + SM_CAND);

    if (tid == 0) {
#pragma unroll
        for (int s = 0; s < NSTAGE; s++) {
            mbar_init(smu + SM_MBAR + s * 8, 64);        // full: 64 producer threads
            mbar_init(smu + SM_MBAR + 32 + s * 8, 16);   // free: 16 consumer warps
        }
    }

    // ---- prologue: A_hi + wsq via cp.async; zsq / margin / counters --------
#pragma unroll
    for (int i = 0; i < 8; i++) {
        int idx = tid + i * THREADS;
        if (idx < 4096) {
            int r = idx >> 5, g = idx & 31;
            uint32_t sw = r * 512 + ((g ^ (r & 7)) << 4);
            cp_async16(smu + SM_AH + sw, g_zh + (((size_t)(rowBase + r)) << 8) + (g << 3));
        }
    }
#pragma unroll
    for (int i = 0; i < 2; i++) {
        int idx = tid + i * THREADS;
        if (idx < 1024) cp_async16(smu + SM_WSQ + idx * 16, g_wsq + idx * 4);
    }
    cp_commit();
    if (tid < TM) {
        float zsv = g_zsq[rowBase + tid];
        zsq_s[tid]  = zsv;
        // rigorous pruning margin: 2*(2^-10 * sqrt(zs) * ||w||max) + slack
        marg_s[tid] = 1.526e-5f * sqrtf(zsv) + 3e-5f;
        runk_s[tid] = 0xFFFFFFFFu;
        cnt_s[tid]  = 0;
    }
    cp_wait<0>();
    __syncthreads();     // A, wsq, zsq, counters visible; mbarriers initialized

    if (wid < 2) {
        // ==================== producers: 64 threads =========================
        const int t = tid;
        int ph = 1;
        for (int it = 0; it < NITER; ++it) {
            const int s = it & (NSTAGE - 1);
            MBAR_WAIT(smu + SM_MBAR + 32 + s * 8, ph);
            if (s == NSTAGE - 1) ph ^= 1;
            const int cb = (it >> 2) * CN;
            const int d0 = (it & 3) * KSUB;
            const uint32_t sB = smu + SM_B + s * STG_SZ;
#pragma unroll
            for (int i = 0; i < 16; i++) {
                int idx = t + i * 64;
                int n = idx >> 3, g = idx & 7;
                uint32_t sw = n * 128 + ((g ^ (n & 7)) << 4);
                cp_async16(sB + sw, g_wh + (((size_t)(cb + n)) << 8) + d0 + (g << 3));
            }
            cp_async_mbar_arrive(smu + SM_MBAR + s * 8);
        }
    } else {
        // ==================== consumers: 16 warps ===========================
        const int cw = wid - 2;
        ConsCtx cx;
        cx.smu = smu;
        cx.wr = cw >> 2;  cx.wc = cw & 3;
        cx.lx = l & 7;    cx.lhi = l >> 4;  cx.l3 = l & 3;  cx.l = l;
        const int l15 = l & 15;
        cx.aBaseH0 = smu + SM_AH + (cx.wr * 32 + l15) * 512;
        cx.aBaseH1 = smu + SM_AH + (cx.wr * 32 + 16 + l15) * 512;
        cx.bBase0 = (uint32_t)((cx.wc * 32 + l15) * 128);
        cx.bBase1 = (uint32_t)((cx.wc * 32 + 16 + l15) * 128);

        float accA[2][4][4], accB[2][4][4];
        float lmA[2][2], lmB[2][2];
        int phF = 0, itg = 0;

        for (int c2 = 0; c2 < NCHUNK; c2 += 2) {
            // ---- chunk c2 -> accA; overlap epilogue of chunk c2-1 (accB) ---
#pragma unroll
            for (int mt = 0; mt < 2; mt++)
#pragma unroll
                for (int nt = 0; nt < 4; nt++)
#pragma unroll
                    for (int j = 0; j < 4; j++) accA[mt][nt][j] = 0.f;
            for (int sub = 0; sub < NSUBC; ++sub, ++itg) {
                const int s = itg & (NSTAGE - 1);
                MBAR_WAIT(smu + SM_MBAR + s * 8, phF);
                if (s == NSTAGE - 1) phF ^= 1;
                do_stage(accA, cx, smu + SM_B + s * STG_SZ, sub);
                if (l == 0) mbar_arrive(smu + SM_MBAR + 32 + s * 8);
                if (c2 > 0 && sub == 0) epi1(accB, lmB, cx, c2 - 1, wsq_s, runk_s);
                if (c2 > 0 && sub == 1) epi2(accB, lmB, cx, c2 - 1, marg_s, runk_s, cnt_s, cand_s);
            }
            // ---- chunk c2+1 -> accB; overlap epilogue of chunk c2 (accA) ---
#pragma unroll
            for (int mt = 0; mt < 2; mt++)
#pragma unroll
                for (int nt = 0; nt < 4; nt++)
#pragma unroll
                    for (int j = 0; j < 4; j++) accB[mt][nt][j] = 0.f;
            for (int sub = 0; sub < NSUBC; ++sub, ++itg) {
                const int s = itg & (NSTAGE - 1);
                MBAR_WAIT(smu + SM_MBAR + s * 8, phF);
                if (s == NSTAGE - 1) phF ^= 1;
                do_stage(accB, cx, smu + SM_B + s * STG_SZ, sub);
                if (l == 0) mbar_arrive(smu + SM_MBAR + 32 + s * 8);
                if (sub == 0) epi1(accA, lmA, cx, c2, wsq_s, runk_s);
                if (sub == 1) epi2(accA, lmA, cx, c2, marg_s, runk_s, cnt_s, cand_s);
            }
        }
        // final chunk's epilogue
        epi1(accB, lmB, cx, NCHUNK - 1, wsq_s, runk_s);
        epi2(accB, lmB, cx, NCHUNK - 1, marg_s, runk_s, cnt_s, cand_s);
    }

    __syncthreads();   // pass-1 complete; candidate lists visible to all warps

    // ==================== pass 2: exact fp32 rescore (all 18 warps) =========
    const float4* w4 = reinterpret_cast<const float4*>(w);
    for (int r = wid; r < TM; r += NWARP) {
        const float zs = zsq_s[r];
        const float4* zr = reinterpret_cast<const float4*>(z) + (size_t)(rowBase + r) * D4;
        const float4 za = zr[l * 2], zb = zr[l * 2 + 1];
        const int cnt = cnt_s[r];
        const bool fullscan = (cnt > CAP);
        const int total = fullscan ? KCODES : cnt;
        float bd = 3.4e38f;
        int   bi = 0x7fffffff;
        for (int i = 0; i < total; i++) {
            const int code = fullscan ? i : (int)cand_s[r * CAP + i];
            const float4* wr4 = w4 + (size_t)code * D4;
            const float4 wa = wr4[l * 2], wb = wr4[l * 2 + 1];
            float p = za.x * wa.x;
            p += za.y * wa.y; p += za.z * wa.z; p += za.w * wa.w;
            p += zb.x * wb.x; p += zb.y * wb.y; p += zb.z * wb.z; p += zb.w * wb.w;
#pragma unroll
            for (int off = 16; off > 0; off >>= 1)
                p += __shfl_xor_sync(0xffffffff, p, off);
            const float dist = (zs - 2.0f * p) + wsq_s[code];
            if (dist < bd || (dist == bd && code < bi)) { bd = dist; bi = code; }
        }
        if (write_idx && l == 0)
            out[(size_t)N * DDIM + rowBase + r] = (float)bi;
        const float4* src = w4 + (size_t)bi * D4;
        float4* dst = reinterpret_cast<float4*>(out) + (size_t)(rowBase + r) * D4;
        dst[l]      = src[l];
        dst[l + 32] = src[l + 32];
    }
}

// -------------------------------------------------------------------------------
extern "C" void kernel_launch(void* const* d_in, const int* in_sizes, int n_in,
                              void* d_out, int out_size) {
    const float* z = (const float*)d_in[0];
    const float* w = (const float*)d_in[1];
    float* out = (float*)d_out;
    const int N = in_sizes[0] / DDIM;

    cudaFuncSetAttribute(vq_main, cudaFuncAttributeMaxDynamicSharedMemorySize, SMEM_TOTAL);
    const int write_idx = (out_size >= N * DDIM + N) ? 1 : 0;

    decomp_w_kernel<<<(KCODES * D4 + 255) / 256, 256>>>((const float4*)w, KCODES * D4);
    wsq_kernel<<<(KCODES + 255) / 256, 256>>>(w);
    zprep_kernel<<<(N + 255) / 256, 256>>>(z, N);
    vq_main<<<N / TM, THREADS, SMEM_TOTAL>>>(z, w, out, N, write_idx);
}

// round 15
// speedup vs baseline: 21.5288x; 1.2679x over previous
#include <cuda_runtime.h>
#include <cuda_fp16.h>
#include <cstdint>

#define DDIM     256
#define D4       64
#define KCODES   4096
#define TM       128          // rows per CTA
#define CN       128          // codes per chunk
#define NCHUNK   (KCODES/CN)  // 32
#define KSUB     64           // dims per stage
#define NSUBC    4            // stages per chunk
#define NITER    (NCHUNK*NSUBC) // 128
#define NSTAGE   4
#define STG_SZ   16384        // B stage bytes (128 codes x 64 dims f16)
#define THREADS  576          // 2 producer + 16 consumer warps
#define NWARP    18
#define MAXROWS  131072
#define CAP      32

// ---------------- device global scratch -------------------------------------
__device__ __half g_zh[(size_t)MAXROWS * DDIM];
__device__ __half g_wh[KCODES * DDIM];
__device__ float  g_wsq[KCODES];
__device__ float  g_zsq[MAXROWS];

// ---------------- smem layout (bytes) ---------------------------------------
#define SM_AH    0            // 65536   A_hi [128][256] f16 swizzled
#define SM_B     65536        // 65536   4 stages x 16384
#define SM_WSQ   131072       // 16384
#define SM_ZSQ   147456       // 512
#define SM_MARG  147968       // 512
#define SM_RUNK  148480       // 512
#define SM_CNT   148992       // 512
#define SM_CAND  149504       // 8192    uint16 [128][32]
#define SM_MBAR  157696       // full[4], free[4]
#define SMEM_TOTAL 157824

// ---------------- asm helpers ------------------------------------------------
__device__ __forceinline__ uint32_t smem_u32(const void* p) {
    uint32_t a;
    asm("{ .reg .u64 t; cvta.to.shared.u64 t, %1; cvt.u32.u64 %0, t; }" : "=r"(a) : "l"(p));
    return a;
}
__device__ __forceinline__ void cp_async16(uint32_t sdst, const void* gsrc) {
    asm volatile("cp.async.cg.shared.global [%0], [%1], 16;\n" :: "r"(sdst), "l"(gsrc));
}
__device__ __forceinline__ void cp_commit() { asm volatile("cp.async.commit_group;\n"); }
template <int NN> __device__ __forceinline__ void cp_wait() {
    asm volatile("cp.async.wait_group %0;\n" :: "n"(NN));
}
__device__ __forceinline__ void mbar_init(uint32_t a, uint32_t cnt) {
    asm volatile("mbarrier.init.shared.b64 [%0], %1;" :: "r"(a), "r"(cnt) : "memory");
}
__device__ __forceinline__ void mbar_arrive(uint32_t a) {
    asm volatile("mbarrier.arrive.shared.b64 _, [%0];" :: "r"(a) : "memory");
}
__device__ __forceinline__ void cp_async_mbar_arrive(uint32_t a) {
    asm volatile("cp.async.mbarrier.arrive.noinc.shared.b64 [%0];" :: "r"(a) : "memory");
}
#define MBAR_WAIT(mbar, parity) do {                                            \
    uint32_t _m = (mbar); uint32_t _p = (parity); uint32_t _done;               \
    asm volatile("{\n\t.reg .pred p;\n\t"                                       \
        "mbarrier.try_wait.parity.acquire.cta.shared::cta.b64 p, [%1], %2;\n\t" \
        "selp.b32 %0, 1, 0, p;\n\t}"                                            \
        : "=r"(_done) : "r"(_m), "r"(_p) : "memory");                           \
    if (!_done) {                                                               \
        asm volatile("{\n\t.reg .pred P1;\n\t"                                  \
            "WL_%=:\n\t"                                                        \
            "mbarrier.try_wait.parity.acquire.cta.shared::cta.b64 P1, [%0], %1, 0x989680;\n\t" \
            "@P1 bra.uni WD_%=;\n\t"                                            \
            "bra.uni WL_%=;\n\t"                                                \
            "WD_%=:\n\t}" :: "r"(_m), "r"(_p) : "memory");                      \
    }                                                                           \
} while (0)
#define LDSM4(r, addr)                                                          \
    asm volatile("ldmatrix.sync.aligned.m8n8.x4.shared.b16 {%0,%1,%2,%3}, [%4];"\
        : "=r"((r)[0]), "=r"((r)[1]), "=r"((r)[2]), "=r"((r)[3]) : "r"(addr))
#define MMA16816(d, a, b)                                                       \
    asm volatile("mma.sync.aligned.m16n8k16.row.col.f32.f16.f16.f32 "           \
        "{%0,%1,%2,%3}, {%4,%5,%6,%7}, {%8,%9}, {%0,%1,%2,%3};"                 \
        : "+f"((d)[0]), "+f"((d)[1]), "+f"((d)[2]), "+f"((d)[3])                \
        : "r"((a)[0]), "r"((a)[1]), "r"((a)[2]), "r"((a)[3]),                   \
          "r"((b)[0]), "r"((b)[1]))

// order-preserving float<->uint key (for atomicMin over signed floats)
__device__ __forceinline__ uint32_t fkey(float f) {
    uint32_t u = __float_as_uint(f);
    return (u >> 31) ? ~u : (u | 0x80000000u);
}
__device__ __forceinline__ float funkey(uint32_t k) {
    return (k & 0x80000000u) ? __uint_as_float(k & 0x7fffffffu)
                             : __uint_as_float(~k);
}

// ---------------- preprocessing ----------------------------------------------
// fused: z -> fp16 hi limb AND z_sq (summation order is part of the proven
// tie structure — do not change)
__global__ void zprep_kernel(const float* __restrict__ z, int N) {
    int n = blockIdx.x * blockDim.x + threadIdx.x;
    if (n < N) {
        const float4* row = reinterpret_cast<const float4*>(z) + (size_t)n * D4;
        uint2* dst = reinterpret_cast<uint2*>(g_zh) + (size_t)n * D4;
        float s = 0.f;
#pragma unroll 8
        for (int i = 0; i < D4; i++) {
            float4 v = row[i];
            s += v.x * v.x; s += v.y * v.y; s += v.z * v.z; s += v.w * v.w;
            __half2 h01 = __halves2half2(__float2half_rn(v.x), __float2half_rn(v.y));
            __half2 h23 = __halves2half2(__float2half_rn(v.z), __float2half_rn(v.w));
            uint2 uh = { *reinterpret_cast<uint32_t*>(&h01),
                         *reinterpret_cast<uint32_t*>(&h23) };
            dst[i] = uh;
        }
        g_zsq[n] = s;
    }
}
__global__ void decomp_w_kernel(const float4* __restrict__ w4, int n4) {
    int i = blockIdx.x * blockDim.x + threadIdx.x;
    if (i < n4) {
        float4 v = w4[i];
        v.x *= 4096.f; v.y *= 4096.f; v.z *= 4096.f; v.w *= 4096.f;  // exact 2^12
        __half2 h01 = __halves2half2(__float2half_rn(v.x), __float2half_rn(v.y));
        __half2 h23 = __halves2half2(__float2half_rn(v.z), __float2half_rn(v.w));
        uint2 uh = { *reinterpret_cast<uint32_t*>(&h01), *reinterpret_cast<uint32_t*>(&h23) };
        reinterpret_cast<uint2*>(g_wh)[i] = uh;
    }
}
__global__ void wsq_kernel(const float* __restrict__ w) {
    int k = blockIdx.x * blockDim.x + threadIdx.x;
    if (k < KCODES) {
        const float4* row = reinterpret_cast<const float4*>(w) + (size_t)k * D4;
        float s = 0.f;
#pragma unroll 8
        for (int i = 0; i < D4; i++) {
            float4 v = row[i];
            s += v.x * v.x; s += v.y * v.y; s += v.z * v.z; s += v.w * v.w;
        }
        g_wsq[k] = s;
    }
}

// ---------------- main fused kernel -------------------------------------------
__global__ __launch_bounds__(THREADS, 1)
void vq_main(const float* __restrict__ z, const float* __restrict__ w,
             float* __restrict__ out, int N, int write_idx) {
    extern __shared__ char sm[];
    const uint32_t smu = smem_u32(sm);
    const int tid  = threadIdx.x;
    const int wid  = tid >> 5;
    const int l    = tid & 31;
    const int rowBase = blockIdx.x * TM;

    float*     wsq_s  = reinterpret_cast<float*>(sm + SM_WSQ);
    float*     zsq_s  = reinterpret_cast<float*>(sm + SM_ZSQ);
    float*     marg_s = reinterpret_cast<float*>(sm + SM_MARG);
    uint32_t*  runk_s = reinterpret_cast<uint32_t*>(sm + SM_RUNK);
    int*       cnt_s  = reinterpret_cast<int*>(sm + SM_CNT);
    uint16_t*  cand_s = reinterpret_cast<uint16_t*>(sm + SM_CAND);

    if (tid == 0) {
#pragma unroll
        for (int s = 0; s < NSTAGE; s++) {
            mbar_init(smu + SM_MBAR + s * 8, 64);        // full: 64 producer threads
            mbar_init(smu + SM_MBAR + 32 + s * 8, 16);   // free: 16 consumer warps
        }
    }

    // ---- prologue: A_hi + wsq via cp.async; zsq / margin / counters --------
#pragma unroll
    for (int i = 0; i < 8; i++) {
        int idx = tid + i * THREADS;
        if (idx < 4096) {
            int r = idx >> 5, g = idx & 31;
            uint32_t sw = r * 512 + ((g ^ (r & 7)) << 4);
            cp_async16(smu + SM_AH + sw, g_zh + (((size_t)(rowBase + r)) << 8) + (g << 3));
        }
    }
#pragma unroll
    for (int i = 0; i < 2; i++) {
        int idx = tid + i * THREADS;
        if (idx < 1024) cp_async16(smu + SM_WSQ + idx * 16, g_wsq + idx * 4);
    }
    cp_commit();
    if (tid < TM) {
        float zsv = g_zsq[rowBase + tid];
        zsq_s[tid]  = zsv;
        // rigorous pruning margin: 2*(2^-10 * sqrt(zs) * ||w||max) + slack
        marg_s[tid] = 1.526e-5f * sqrtf(zsv) + 3e-5f;
        runk_s[tid] = 0xFFFFFFFFu;
        cnt_s[tid]  = 0;
    }
    cp_wait<0>();
    __syncthreads();     // A, wsq, zsq, counters visible; mbarriers initialized

    if (wid < 2) {
        // ==================== producers: 64 threads =========================
        const int t = tid;
        int ph = 1;
        for (int it = 0; it < NITER; ++it) {
            const int s = it & (NSTAGE - 1);
            MBAR_WAIT(smu + SM_MBAR + 32 + s * 8, ph);
            if (s == NSTAGE - 1) ph ^= 1;
            const int cb = (it >> 2) * CN;
            const int d0 = (it & 3) * KSUB;
            const uint32_t sB = smu + SM_B + s * STG_SZ;
#pragma unroll
            for (int i = 0; i < 16; i++) {
                int idx = t + i * 64;
                int n = idx >> 3, g = idx & 7;
                uint32_t sw = n * 128 + ((g ^ (n & 7)) << 4);
                cp_async16(sB + sw, g_wh + (((size_t)(cb + n)) << 8) + d0 + (g << 3));
            }
            cp_async_mbar_arrive(smu + SM_MBAR + s * 8);
        }
    } else {
        // ==================== consumers: 16 warps ===========================
        const int cw = wid - 2;
        const int wr = cw >> 2;       // 0..3  (32 rows each)
        const int wc = cw & 3;        // 0..3  (32 codes each)
        const int lx = l & 7, lhi = l >> 4, l3 = l & 3, l15 = l & 15;

        uint32_t aBaseH[2];
#pragma unroll
        for (int mt = 0; mt < 2; mt++)
            aBaseH[mt] = smu + SM_AH + (wr * 32 + mt * 16 + l15) * 512;
        uint32_t bBase[2];
#pragma unroll
        for (int p = 0; p < 2; p++)
            bBase[p] = (uint32_t)((wc * 32 + p * 16 + l15) * 128);

        float acc[2][4][4];
        int phF = 0, itg = 0;

        for (int c = 0; c < NCHUNK; ++c) {
#pragma unroll
            for (int mt = 0; mt < 2; mt++)
#pragma unroll
                for (int nt = 0; nt < 4; nt++)
#pragma unroll
                    for (int j = 0; j < 4; j++) acc[mt][nt][j] = 0.f;

            for (int sub = 0; sub < NSUBC; ++sub, ++itg) {
                const int s = itg & (NSTAGE - 1);
                MBAR_WAIT(smu + SM_MBAR + s * 8, phF);
                if (s == NSTAGE - 1) phF ^= 1;
                const uint32_t stg = smu + SM_B + s * STG_SZ;
#pragma unroll
                for (int h = 0; h < 4; ++h) {     // 4 x 16-dim slices per stage
                    uint32_t ah[2][4], bh[4][2];
                    const uint32_t cxa =
                        (uint32_t)(((sub * 8 + h * 2 + lhi) ^ lx) << 4);
#pragma unroll
                    for (int mt = 0; mt < 2; mt++) LDSM4(ah[mt], aBaseH[mt] + cxa);
                    const uint32_t ob = (uint32_t)(((h * 2 + lhi) ^ lx) << 4);
#pragma unroll
                    for (int p = 0; p < 2; p++) {
                        uint32_t tmp[4];
                        LDSM4(tmp, stg + bBase[p] + ob);
                        bh[2 * p][0] = tmp[0]; bh[2 * p][1] = tmp[2];
                        bh[2 * p + 1][0] = tmp[1]; bh[2 * p + 1][1] = tmp[3];
                    }
#pragma unroll
                    for (int mt = 0; mt < 2; mt++)
#pragma unroll
                        for (int nt = 0; nt < 4; nt++)
                            MMA16816(acc[mt][nt], ah[mt], bh[nt]);
                }
                if (l == 0) mbar_arrive(smu + SM_MBAR + 32 + s * 8);
            }

            // ---- epilogue: E'(k) = wsq - 2*dot estimate; margin collect ----
            const int cb = c * CN + wc * 32 + l3 * 2;
            // convert acc -> E in place, fused with per-group local min
            float lm[2][2];
#pragma unroll
            for (int mt = 0; mt < 2; mt++)
#pragma unroll
                for (int rh = 0; rh < 2; rh++) {
                    float m = 3.4e38f;
#pragma unroll
                    for (int nt = 0; nt < 4; nt++)
#pragma unroll
                        for (int cc = 0; cc < 2; cc++) {
                            float e = fmaf(acc[mt][nt][rh * 2 + cc], -0x1p-11f,
                                           wsq_s[cb + nt * 8 + cc]);
                            acc[mt][nt][rh * 2 + cc] = e;
                            m = (e < m) ? e : m;
                        }
                    lm[mt][rh] = m;
                    const int row = wr * 32 + mt * 16 + (l >> 2) + rh * 8;
                    const uint32_t key = fkey(m);
                    if (key < runk_s[row]) atomicMin(&runk_s[row], key);
                }
            // phase 2: collect candidates, gated by group-local min
#pragma unroll
            for (int mt = 0; mt < 2; mt++)
#pragma unroll
                for (int rh = 0; rh < 2; rh++) {
                    const int row = wr * 32 + mt * 16 + (l >> 2) + rh * 8;
                    const float thr = funkey(runk_s[row]) + marg_s[row];
                    if (lm[mt][rh] <= thr) {
#pragma unroll
                        for (int nt = 0; nt < 4; nt++)
#pragma unroll
                            for (int cc = 0; cc < 2; cc++) {
                                const float e = acc[mt][nt][rh * 2 + cc];
                                if (e <= thr) {
                                    int pos = atomicAdd(&cnt_s[row], 1);
                                    if (pos < CAP)
                                        cand_s[row * CAP + pos] =
                                            (uint16_t)(cb + nt * 8 + cc);
                                }
                            }
                    }
                }
        }
    }

    __syncthreads();   // pass-1 complete; candidate lists visible to all warps

    // ==================== pass 2: exact fp32 rescore (all 18 warps) =========
    const float4* w4 = reinterpret_cast<const float4*>(w);
    for (int r = wid; r < TM; r += NWARP) {
        const float zs = zsq_s[r];
        const float4* zr = reinterpret_cast<const float4*>(z) + (size_t)(rowBase + r) * D4;
        const float4 za = zr[l * 2], zb = zr[l * 2 + 1];
        const int cnt = cnt_s[r];
        const bool fullscan = (cnt > CAP);
        const int total = fullscan ? KCODES : cnt;
        float bd = 3.4e38f;
        int   bi = 0x7fffffff;
        for (int i = 0; i < total; i++) {
            const int code = fullscan ? i : (int)cand_s[r * CAP + i];
            const float4* wr4 = w4 + (size_t)code * D4;
            const float4 wa = wr4[l * 2], wb = wr4[l * 2 + 1];
            float p = za.x * wa.x;
            p += za.y * wa.y; p += za.z * wa.z; p += za.w * wa.w;
            p += zb.x * wb.x; p += zb.y * wb.y; p += zb.z * wb.z; p += zb.w * wb.w;
#pragma unroll
            for (int off = 16; off > 0; off >>= 1)
                p += __shfl_xor_sync(0xffffffff, p, off);
            const float dist = (zs - 2.0f * p) + wsq_s[code];
            if (dist < bd || (dist == bd && code < bi)) { bd = dist; bi = code; }
        }
        if (write_idx && l == 0)
            out[(size_t)N * DDIM + rowBase + r] = (float)bi;
        const float4* src = w4 + (size_t)bi * D4;
        float4* dst = reinterpret_cast<float4*>(out) + (size_t)(rowBase + r) * D4;
        dst[l]      = src[l];
        dst[l + 32] = src[l + 32];
    }
}

// -------------------------------------------------------------------------------
extern "C" void kernel_launch(void* const* d_in, const int* in_sizes, int n_in,
                              void* d_out, int out_size) {
    const float* z = (const float*)d_in[0];
    const float* w = (const float*)d_in[1];
    float* out = (float*)d_out;
    const int N = in_sizes[0] / DDIM;

    cudaFuncSetAttribute(vq_main, cudaFuncAttributeMaxDynamicSharedMemorySize, SMEM_TOTAL);
    const int write_idx = (out_size >= N * DDIM + N) ? 1 : 0;

    decomp_w_kernel<<<(KCODES * D4 + 255) / 256, 256>>>((const float4*)w, KCODES * D4);
    wsq_kernel<<<(KCODES + 255) / 256, 256>>>(w);
    zprep_kernel<<<(N + 255) / 256, 256>>>(z, N);
    vq_main<<<N / TM, THREADS, SMEM_TOTAL>>>(z, w, out, N, write_idx);
}